// round 14
// baseline (speedup 1.0000x reference)
#include <cuda_runtime.h>

#define INV_SQRT_2PI 0.3989422804014327f

// hess_gelu: (2 - 2*x^2) * exp(-x^2/2)/sqrt(2*pi), elementwise over 2^28 fp32.
// Pure streaming kernel: 1 GiB read + 1 GiB write, zero reuse.
// Runs at ~7.0 TB/s (88% DRAM) — the mixed R/W HBM3e pin ceiling. Verified
// invariant across cache policy, access width (128/256b), block size, MLP 4-8,
// and occupancy 61-79%; the only binding resource is DRAM bandwidth.
// n = 2^28 floats = 2^26 float4 = 65536 blocks * 256 threads * 4 float4/thread.
#define THREADS 256
#define VPT 4  // float4 per thread

__device__ __forceinline__ float hess(float x) {
    float t = x * x;
    return (2.0f - 2.0f * t) * (INV_SQRT_2PI * __expf(-0.5f * t));
}

__global__ void __launch_bounds__(THREADS) hess_gelu_kernel(
    const float4* __restrict__ x, float4* __restrict__ out)
{
    // Block-contiguous tile of THREADS*VPT float4s; thread accesses are
    // block-strided so each of the VPT loads is fully coalesced and the
    // 4 front-batched LDG.128s give MLP_p1=4 per thread.
    size_t base = (size_t)blockIdx.x * (THREADS * VPT) + threadIdx.x;

    float4 v[VPT];
#pragma unroll
    for (int j = 0; j < VPT; j++) {
        v[j] = x[base + j * THREADS];   // LDG.E.128
    }

#pragma unroll
    for (int j = 0; j < VPT; j++) {
        v[j].x = hess(v[j].x);
        v[j].y = hess(v[j].y);
        v[j].z = hess(v[j].z);
        v[j].w = hess(v[j].w);
    }

#pragma unroll
    for (int j = 0; j < VPT; j++) {
        out[base + j * THREADS] = v[j]; // STG.E.128
    }
}

extern "C" void kernel_launch(void* const* d_in, const int* in_sizes, int n_in,
                              void* d_out, int out_size)
{
    const float* x = (const float*)d_in[0];
    float* out = (float*)d_out;
    int n = in_sizes[0];                 // 268435456
    int n4 = n >> 2;                     // 2^26 float4
    int blocks = n4 / (THREADS * VPT);   // 65536, exact
    hess_gelu_kernel<<<blocks, THREADS>>>((const float4*)x, (float4*)out);
}

// round 16
// speedup vs baseline: 1.0063x; 1.0063x over previous
#include <cuda_runtime.h>

#define INV_SQRT_2PI 0.3989422804014327f

// A/B probe: write-through stores (st.global.wt) — streams writes toward DRAM
// without L2 dirty-line writeback batching. Loads default policy. Otherwise
// identical to the 305.6us best (256t, VPT=4, exact grid).
// n = 2^28 floats = 2^26 float4 = 65536 blocks * 256 threads * 4 float4/thread.
#define THREADS 256
#define VPT 4  // float4 per thread

__device__ __forceinline__ float hess(float x) {
    float t = x * x;
    return (2.0f - 2.0f * t) * (INV_SQRT_2PI * __expf(-0.5f * t));
}

__global__ void __launch_bounds__(THREADS) hess_gelu_kernel(
    const float4* __restrict__ x, float4* __restrict__ out)
{
    size_t base = (size_t)blockIdx.x * (THREADS * VPT) + threadIdx.x;

    float4 v[VPT];
#pragma unroll
    for (int j = 0; j < VPT; j++) {
        v[j] = x[base + j * THREADS];   // default-policy LDG.E.128
    }

#pragma unroll
    for (int j = 0; j < VPT; j++) {
        v[j].x = hess(v[j].x);
        v[j].y = hess(v[j].y);
        v[j].z = hess(v[j].z);
        v[j].w = hess(v[j].w);
    }

#pragma unroll
    for (int j = 0; j < VPT; j++) {
        float4* p = out + base + j * THREADS;
        asm volatile("st.global.wt.v4.f32 [%0], {%1,%2,%3,%4};"
                     :: "l"(p), "f"(v[j].x), "f"(v[j].y), "f"(v[j].z), "f"(v[j].w)
                     : "memory");
    }
}

extern "C" void kernel_launch(void* const* d_in, const int* in_sizes, int n_in,
                              void* d_out, int out_size)
{
    const float* x = (const float*)d_in[0];
    float* out = (float*)d_out;
    int n = in_sizes[0];                 // 268435456
    int n4 = n >> 2;                     // 2^26 float4
    int blocks = n4 / (THREADS * VPT);   // 65536, exact
    hess_gelu_kernel<<<blocks, THREADS>>>((const float4*)x, (float4*)out);
}